// round 1
// baseline (speedup 1.0000x reference)
#include <cuda_runtime.h>
#include <math.h>

#define NB 32
#define NG 50
#define NA 8400
#define NC 80
#define NCH 85
#define FLT_BIG 3.402823466e+38f

// -------- scratch (static device globals; no runtime allocation) --------
__device__ float4 d_box[NB*NA];                  // decoded boxes (cx,cy,w,h)
__device__ float  d_objl[NB*NA];                 // obj logits
__device__ float  d_sobj[NB*NA];                 // sigmoid(obj)
__device__ float  d_s[NB*NA];                    // per fg-slot: sum_c log1p(-p_c)
__device__ int    d_fgidx[NB*NA];                // compacted fg anchor ids
__device__ int    d_nfg[NB];
__device__ unsigned long long d_geom[NB*NA];     // geom bitmask over 50 gts
__device__ unsigned long long d_vmask[NB];       // valid-gt bitmask
__device__ float  d_cost[NB*NG*NA];              // [b][g][fg-slot]
__device__ float  d_iouM[NB*NG*NA];
__device__ float  d_thr[NB*NG];
__device__ double d_acc[4];                      // iou, obj, cls, num_fg

__device__ __forceinline__ void anchor_info(int a, int& H, float& fs, int& cell) {
    if (a < 6400)      { H = 80; fs = 8.f;  cell = a; }
    else if (a < 8000) { H = 40; fs = 16.f; cell = a - 6400; }
    else               { H = 20; fs = 32.f; cell = a - 8000; }
}
__device__ __forceinline__ const float* lvl_ptr(int a, const float* o0, const float* o1, const float* o2) {
    return a < 6400 ? o0 : (a < 8000 ? o1 : o2);
}
__device__ __forceinline__ double warp_sum(double v) {
    #pragma unroll
    for (int o = 16; o; o >>= 1) v += __shfl_down_sync(0xffffffffu, v, o);
    return v;
}

// -------- K0: zero accumulators, compute valid-gt bitmask --------
__global__ void k_init(const float* __restrict__ labels) {
    int b = blockIdx.x, g = threadIdx.x;
    __shared__ unsigned long long m;
    if (g == 0) {
        m = 0ull;
        d_nfg[b] = 0;
        if (b == 0) { d_acc[0]=0.0; d_acc[1]=0.0; d_acc[2]=0.0; d_acc[3]=0.0; }
    }
    __syncthreads();
    if (g < NG) {
        const float* L = labels + (b*NG + g)*5;
        float s = L[0]+L[1]+L[2]+L[3]+L[4];
        if (s > 0.f) atomicOr(&m, 1ull << g);
    }
    __syncthreads();
    if (g == 0) d_vmask[b] = m;
}

// -------- K1: decode anchors, geometry masks, fg compaction --------
__global__ void k_anchor(const float* __restrict__ o0, const float* __restrict__ o1,
                         const float* __restrict__ o2, const float* __restrict__ labels) {
    int t = blockIdx.x*blockDim.x + threadIdx.x;
    if (t >= NB*NA) return;
    int b = t / NA, a = t % NA;
    int H, cell; float fs;
    anchor_info(a, H, fs, cell);
    const float* o = lvl_ptr(a, o0, o1, o2);
    int chs = H*H;
    int base = b*NCH*chs + cell;
    float v0 = o[base], v1 = o[base+chs], v2 = o[base+2*chs],
          v3 = o[base+3*chs], v4 = o[base+4*chs];
    int x = cell % H, y = cell / H;
    float4 bx;
    bx.x = (v0 + (float)x)*fs;
    bx.y = (v1 + (float)y)*fs;
    bx.z = expf(v2)*fs;
    bx.w = expf(v3)*fs;
    d_box[t] = bx;
    d_objl[t] = v4;
    d_sobj[t] = 1.f/(1.f + expf(-v4));

    float cx = ((float)x + 0.5f)*fs, cy = ((float)y + 0.5f)*fs, rs = 2.5f*fs;
    unsigned long long geom = 0ull, vm = d_vmask[b];
    bool fgany = false;
    for (int g = 0; g < NG; ++g) {
        const float* L = labels + (b*NG + g)*5;
        float gx = L[1], gy = L[2], gw = L[3], gh = L[4];
        bool inb = (cx > gx - 0.5f*gw) && (cx < gx + 0.5f*gw) &&
                   (cy > gy - 0.5f*gh) && (cy < gy + 0.5f*gh);
        bool inc = (fabsf(cx - gx) < rs) && (fabsf(cy - gy) < rs);
        if (inb && inc) geom |= 1ull << g;
        if ((inb || inc) && ((vm >> g) & 1ull)) fgany = true;
    }
    d_geom[t] = geom;
    if (fgany) {
        int slot = atomicAdd(&d_nfg[b], 1);
        d_fgidx[b*NA + slot] = a;
    }
}

// -------- K2: per fg anchor: s = sum_c log1p(-p_c) --------
__global__ void k_s(const float* __restrict__ o0, const float* __restrict__ o1,
                    const float* __restrict__ o2) {
    int b = blockIdx.y;
    int j = blockIdx.x*blockDim.x + threadIdx.x;
    if (j >= d_nfg[b]) return;
    int a = d_fgidx[b*NA + j];
    int H, cell; float fs;
    anchor_info(a, H, fs, cell);
    const float* o = lvl_ptr(a, o0, o1, o2);
    int chs = H*H;
    int base = (b*NCH + 5)*chs + cell;
    float sobj = d_sobj[b*NA + a];
    float s = 0.f;
    for (int c = 0; c < NC; ++c) {
        float xl = o[base + c*chs];
        float sc = 1.f/(1.f + expf(-xl));
        float p = sqrtf(sc * sobj);
        p = fminf(fmaxf(p, 1e-7f), 1.f - 1e-6f);
        s += log1pf(-p);
    }
    d_s[b*NA + j] = s;
}

// -------- K3: cost + iou matrix over (valid g) x (fg anchors) --------
__global__ void k_cost(const float* __restrict__ o0, const float* __restrict__ o1,
                       const float* __restrict__ o2, const float* __restrict__ labels) {
    int b = blockIdx.y, g = blockIdx.x;
    if (!((d_vmask[b] >> g) & 1ull)) return;
    const float* L = labels + (b*NG + g)*5;
    int cls = (int)L[0];
    float gx = L[1], gy = L[2], gw = L[3], gh = L[4];
    float ga = gw*gh;
    float gx0 = gx - 0.5f*gw, gx1 = gx + 0.5f*gw;
    float gy0 = gy - 0.5f*gh, gy1 = gy + 0.5f*gh;
    int n = d_nfg[b];
    int rowbase = (b*NG + g)*NA;
    for (int j = threadIdx.x; j < n; j += blockDim.x) {
        int a = d_fgidx[b*NA + j];
        float4 bx = d_box[b*NA + a];
        float px0 = bx.x - 0.5f*bx.z, px1 = bx.x + 0.5f*bx.z;
        float py0 = bx.y - 0.5f*bx.w, py1 = bx.y + 0.5f*bx.w;
        float tlx = fmaxf(gx0, px0), tly = fmaxf(gy0, py0);
        float brx = fminf(gx1, px1), bry = fminf(gy1, py1);
        float en = (tlx < brx && tly < bry) ? 1.f : 0.f;
        float inter = (brx - tlx)*(bry - tly)*en;
        float iou = inter / (ga + bx.z*bx.w - inter + 1e-12f);

        int H, cell; float fs;
        anchor_info(a, H, fs, cell);
        const float* o = lvl_ptr(a, o0, o1, o2);
        int chs = H*H;
        float xl = o[(b*NCH + 5 + cls)*chs + cell];
        float sc = 1.f/(1.f + expf(-xl));
        float p = sqrtf(sc * d_sobj[b*NA + a]);
        p = fminf(fmaxf(p, 1e-7f), 1.f - 1e-6f);
        float cls_cost = -logf(p) + log1pf(-p) - d_s[b*NA + j];
        float geomterm = ((d_geom[b*NA + a] >> g) & 1ull) ? 0.f : 100000.f;
        float cost = cls_cost + 3.f*(-logf(iou + 1e-8f)) + geomterm;
        d_cost[rowbase + j] = cost;
        d_iouM[rowbase + j] = iou;
    }
}

// -------- K4: per (b,g): dyn_k from top-10 iou, thr = kth smallest cost --------
__global__ void k_thr() {
    int b = blockIdx.y, g = blockIdx.x;
    int gi = b*NG + g;
    int lane = threadIdx.x;
    if (!((d_vmask[b] >> g) & 1ull)) {
        if (lane == 0) d_thr[gi] = -FLT_BIG;
        return;
    }
    int n = d_nfg[b];
    float ti[10], tc[10];
    #pragma unroll
    for (int i = 0; i < 10; ++i) { ti[i] = 0.f; tc[i] = FLT_BIG; }
    int rowbase = gi*NA;
    for (int j = lane; j < n; j += 32) {
        float v = d_iouM[rowbase + j];
        #pragma unroll
        for (int i = 0; i < 10; ++i) { if (v > ti[i]) { float t = ti[i]; ti[i] = v; v = t; } }
        float c = d_cost[rowbase + j];
        #pragma unroll
        for (int i = 0; i < 10; ++i) { if (c < tc[i]) { float t = tc[i]; tc[i] = c; c = t; } }
    }
    __shared__ float si[320], sc[320];
    #pragma unroll
    for (int i = 0; i < 10; ++i) { si[lane*10 + i] = ti[i]; sc[lane*10 + i] = tc[i]; }
    __syncwarp();
    if (lane == 0) {
        float mi[10], mc[10];
        #pragma unroll
        for (int i = 0; i < 10; ++i) { mi[i] = 0.f; mc[i] = FLT_BIG; }
        for (int k = 0; k < 320; ++k) {
            float v = si[k];
            #pragma unroll
            for (int i = 0; i < 10; ++i) { if (v > mi[i]) { float t = mi[i]; mi[i] = v; v = t; } }
            float c = sc[k];
            #pragma unroll
            for (int i = 0; i < 10; ++i) { if (c < mc[i]) { float t = mc[i]; mc[i] = c; c = t; } }
        }
        float sum = 0.f;
        #pragma unroll
        for (int i = 0; i < 10; ++i) sum += mi[i];
        int dk = (int)sum;
        if (dk < 1) dk = 1;
        if (dk > 10) dk = 10;
        d_thr[gi] = mc[dk - 1];
    }
}

// -------- K5: final match + fg losses (iou, cls, obj-correction, num_fg) --------
__global__ void k_assign(const float* __restrict__ o0, const float* __restrict__ o1,
                         const float* __restrict__ o2, const float* __restrict__ labels) {
    int b = blockIdx.y;
    int j = blockIdx.x*blockDim.x + threadIdx.x;
    double li = 0.0, lo = 0.0, lc = 0.0, lf = 0.0;
    if (j < d_nfg[b]) {
        int a = d_fgidx[b*NA + j];
        unsigned long long vm = d_vmask[b];
        unsigned long long mmask = 0ull;
        int cnt = 0, bestg = 0;
        float best = FLT_BIG;
        for (int g = 0; g < NG; ++g) {
            if (!((vm >> g) & 1ull)) continue;
            float c = d_cost[(b*NG + g)*NA + j];
            if (c < best) { best = c; bestg = g; }
            if (c <= d_thr[b*NG + g]) { mmask |= 1ull << g; cnt++; }
        }
        if (cnt > 1) mmask &= (1ull << bestg);
        if (mmask) {
            int mgt = __ffsll((long long)mmask) - 1;
            float piou = d_iouM[(b*NG + mgt)*NA + j];
            lf = 1.0;
            lo = -(double)d_objl[b*NA + a];              // bce(x,1)-bce(x,0) = -x
            const float* L = labels + (b*NG + mgt)*5;
            float tx = L[1], ty = L[2], tw = L[3], th = L[4];
            float4 pb = d_box[b*NA + a];
            float tlx = fmaxf(pb.x - 0.5f*pb.z, tx - 0.5f*tw);
            float tly = fmaxf(pb.y - 0.5f*pb.w, ty - 0.5f*th);
            float brx = fminf(pb.x + 0.5f*pb.z, tx + 0.5f*tw);
            float bry = fminf(pb.y + 0.5f*pb.w, ty + 0.5f*th);
            float en = (tlx < brx && tly < bry) ? 1.f : 0.f;
            float iw = fmaxf(brx - tlx, 0.f), ih = fmaxf(bry - tly, 0.f);
            float inter = iw*ih*en;
            float uni = pb.z*pb.w + tw*th - inter + 1e-16f;
            float iou = inter/uni;
            li = (double)(1.f - iou*iou);
            int mcls = (int)L[0];
            int H, cell; float fs;
            anchor_info(a, H, fs, cell);
            const float* o = lvl_ptr(a, o0, o1, o2);
            int chs = H*H;
            int base = (b*NCH + 5)*chs + cell;
            float csum = 0.f;
            for (int c = 0; c < NC; ++c) {
                float xl = o[base + c*chs];
                csum += fmaxf(xl, 0.f) + log1pf(expf(-fabsf(xl)));
            }
            csum -= o[base + mcls*chs] * piou;            // -x*y term at target class
            lc = (double)csum;
        }
    }
    li = warp_sum(li); lo = warp_sum(lo); lc = warp_sum(lc); lf = warp_sum(lf);
    if ((threadIdx.x & 31) == 0) {
        if (li != 0.0) atomicAdd(&d_acc[0], li);
        if (lo != 0.0) atomicAdd(&d_acc[1], lo);
        if (lc != 0.0) atomicAdd(&d_acc[2], lc);
        if (lf != 0.0) atomicAdd(&d_acc[3], lf);
    }
}

// -------- K6: dense obj BCE with target 0 over all anchors --------
__global__ void k_obj() {
    int t = blockIdx.x*blockDim.x + threadIdx.x;
    double v = 0.0;
    if (t < NB*NA) {
        float x = d_objl[t];
        v = (double)(fmaxf(x, 0.f) + log1pf(expf(-fabsf(x))));
    }
    v = warp_sum(v);
    if ((threadIdx.x & 31) == 0) atomicAdd(&d_acc[1], v);
}

// -------- K7: combine --------
__global__ void k_final(float* out) {
    double nf = d_acc[3];
    if (nf < 1.0) nf = 1.0;
    out[0] = (float)((5.0*d_acc[0] + d_acc[1] + d_acc[2]) / nf);
}

extern "C" void kernel_launch(void* const* d_in, const int* in_sizes, int n_in,
                              void* d_out, int out_size) {
    const float* o0 = (const float*)d_in[0];
    const float* o1 = (const float*)d_in[1];
    const float* o2 = (const float*)d_in[2];
    const float* lb = (const float*)d_in[3];

    k_init<<<NB, 64>>>(lb);
    k_anchor<<<(NB*NA + 255)/256, 256>>>(o0, o1, o2, lb);
    k_s<<<dim3((NA + 127)/128, NB), 128>>>(o0, o1, o2);
    k_cost<<<dim3(NG, NB), 128>>>(o0, o1, o2, lb);
    k_thr<<<dim3(NG, NB), 32>>>();
    k_assign<<<dim3((NA + 127)/128, NB), 128>>>(o0, o1, o2, lb);
    k_obj<<<(NB*NA + 255)/256, 256>>>();
    k_final<<<1, 1>>>((float*)d_out);
}

// round 2
// speedup vs baseline: 2.2960x; 2.2960x over previous
#include <cuda_runtime.h>
#include <math.h>

#define NB 32
#define NG 50
#define NA 8400
#define NC 80
#define NCH 85
#define NBLK 33            // ceil(8400/256)
#define FLT_BIG 3.402823466e+38f

// -------- scratch (static device globals) --------
__device__ float4 d_box[NB*NA];                  // decoded boxes (full)
__device__ float  d_objl[NB*NA];                 // obj logits (full)
__device__ float  d_sobj[NB*NA];                 // sigmoid(obj) (full)
__device__ unsigned long long d_geom[NB*NA];     // geom bitmask (full)
__device__ unsigned int d_ball[NB*NBLK*8];       // fg ballots per warp
__device__ int    d_bcnt[NB*NBLK];               // fg count per block
__device__ int    d_nfg[NB];
__device__ unsigned long long d_vmask[NB];

// compacted (sorted by anchor id)
__device__ int    d_fa[NB*NA];                   // anchor id per slot
__device__ float4 d_fbox[NB*NA];
__device__ float  d_fsobj[NB*NA];
__device__ unsigned long long d_fgeom[NB*NA];
__device__ float  d_s[NB*NA];                    // sum_c log1p(-p_c)
__device__ float  d_V[NB*NC*NA];                 // [b][c][j]: log1mp - logp
__device__ float2 d_ci[NB*NG*NA];                // (cost, iou)
__device__ float  d_thr[NB*NG];
__device__ double d_acc[4];                      // iou, obj, cls, num_fg

__device__ __forceinline__ void anchor_info(int a, int& H, float& fs, int& cell) {
    if (a < 6400)      { H = 80; fs = 8.f;  cell = a; }
    else if (a < 8000) { H = 40; fs = 16.f; cell = a - 6400; }
    else               { H = 20; fs = 32.f; cell = a - 8000; }
}
__device__ __forceinline__ const float* lvl_ptr(int a, const float* o0, const float* o1, const float* o2) {
    return a < 6400 ? o0 : (a < 8000 ? o1 : o2);
}
__device__ __forceinline__ double warp_sum(double v) {
    #pragma unroll
    for (int o = 16; o; o >>= 1) v += __shfl_down_sync(0xffffffffu, v, o);
    return v;
}
__device__ __forceinline__ void ins_min(float (&t)[10], float v) {
    #pragma unroll
    for (int i = 0; i < 10; ++i) { if (v < t[i]) { float tmp = t[i]; t[i] = v; v = tmp; } }
}
__device__ __forceinline__ void ins_max(float (&t)[10], float v) {
    #pragma unroll
    for (int i = 0; i < 10; ++i) { if (v > t[i]) { float tmp = t[i]; t[i] = v; v = tmp; } }
}

// -------- K0: vmask + zero accumulators --------
__global__ void k_init(const float* __restrict__ labels) {
    int b = blockIdx.x, g = threadIdx.x;
    __shared__ unsigned long long m;
    if (g == 0) {
        m = 0ull;
        d_nfg[b] = 0;
        if (b == 0) { d_acc[0]=0.0; d_acc[1]=0.0; d_acc[2]=0.0; d_acc[3]=0.0; }
    }
    __syncthreads();
    if (g < NG) {
        const float* L = labels + (b*NG + g)*5;
        float s = L[0]+L[1]+L[2]+L[3]+L[4];
        if (s > 0.f) atomicOr(&m, 1ull << g);
    }
    __syncthreads();
    if (g == 0) d_vmask[b] = m;
}

// -------- K1: decode + geometry + fg ballots + dense obj BCE --------
__global__ void k_anchor(const float* __restrict__ o0, const float* __restrict__ o1,
                         const float* __restrict__ o2, const float* __restrict__ labels) {
    int b = blockIdx.y, blk = blockIdx.x, tid = threadIdx.x;
    int a = blk*256 + tid;
    __shared__ float Lx[NG], Ly[NG], Lw[NG], Lh[NG];
    __shared__ int wcnt[8];
    __shared__ double wobj[8];
    if (tid < NG) {
        const float* L = labels + (b*NG + tid)*5;
        Lx[tid] = L[1]; Ly[tid] = L[2]; Lw[tid] = L[3]; Lh[tid] = L[4];
    }
    __syncthreads();

    bool inrange = (a < NA);
    bool fgany = false;
    double objv = 0.0;
    if (inrange) {
        int H, cell; float fs;
        anchor_info(a, H, fs, cell);
        const float* o = lvl_ptr(a, o0, o1, o2);
        int chs = H*H;
        int base = b*NCH*chs + cell;
        float v0 = o[base], v1 = o[base+chs], v2 = o[base+2*chs],
              v3 = o[base+3*chs], v4 = o[base+4*chs];
        int x = cell % H, y = cell / H;
        float4 bx;
        bx.x = (v0 + (float)x)*fs;
        bx.y = (v1 + (float)y)*fs;
        bx.z = __expf(v2)*fs;
        bx.w = __expf(v3)*fs;
        int t = b*NA + a;
        d_box[t] = bx;
        d_objl[t] = v4;
        d_sobj[t] = __fdividef(1.f, 1.f + __expf(-v4));
        // dense obj BCE(x, 0) = max(x,0) + log1p(exp(-|x|))
        objv = (double)(fmaxf(v4, 0.f) + __logf(1.f + __expf(-fabsf(v4))));

        float cx = ((float)x + 0.5f)*fs, cy = ((float)y + 0.5f)*fs, rs = 2.5f*fs;
        unsigned long long geom = 0ull, vm = d_vmask[b];
        #pragma unroll 2
        for (int g = 0; g < NG; ++g) {
            float gx = Lx[g], gy = Ly[g], gw = Lw[g], gh = Lh[g];
            bool inb = (cx > gx - 0.5f*gw) && (cx < gx + 0.5f*gw) &&
                       (cy > gy - 0.5f*gh) && (cy < gy + 0.5f*gh);
            bool inc = (fabsf(cx - gx) < rs) && (fabsf(cy - gy) < rs);
            if (inb && inc) geom |= 1ull << g;
            if ((inb || inc) && ((vm >> g) & 1ull)) fgany = true;
        }
        d_geom[t] = geom;
    }
    unsigned int word = __ballot_sync(0xffffffffu, fgany);
    int w = tid >> 5, lane = tid & 31;
    objv = warp_sum(objv);
    if (lane == 0) {
        d_ball[(b*NBLK + blk)*8 + w] = word;
        wcnt[w] = __popc(word);
        wobj[w] = objv;
    }
    __syncthreads();
    if (tid == 0) {
        int s = 0; double ob = 0.0;
        #pragma unroll
        for (int k = 0; k < 8; ++k) { s += wcnt[k]; ob += wobj[k]; }
        d_bcnt[b*NBLK + blk] = s;
        atomicAdd(&d_nfg[b], s);
        atomicAdd(&d_acc[1], ob);
    }
}

// -------- K2: globally ordered compaction --------
__global__ void k_compact() {
    int b = blockIdx.y, blk = blockIdx.x, tid = threadIdx.x;
    int w = tid >> 5, lane = tid & 31;
    __shared__ int woff[8];
    unsigned int word = d_ball[(b*NBLK + blk)*8 + w];
    __syncthreads();
    if (tid == 0) {
        int s = 0;
        for (int k = 0; k < blk; ++k) s += d_bcnt[b*NBLK + k];
        int r = s;
        for (int k = 0; k < 8; ++k) {
            woff[k] = r;
            r += __popc(d_ball[(b*NBLK + blk)*8 + k]);
        }
    }
    __syncthreads();
    if ((word >> lane) & 1u) {
        int j = woff[w] + __popc(word & ((1u << lane) - 1u));
        int a = blk*256 + tid;
        int t = b*NA + a;
        int fj = b*NA + j;
        d_fa[fj] = a;
        d_fbox[fj] = d_box[t];
        d_fsobj[fj] = d_sobj[t];
        d_fgeom[fj] = d_geom[t];
    }
}

// -------- K3: per fg anchor: s + V[c] for all classes --------
__global__ void k_s(const float* __restrict__ o0, const float* __restrict__ o1,
                    const float* __restrict__ o2) {
    int b = blockIdx.y;
    int j = blockIdx.x*blockDim.x + threadIdx.x;
    if (j >= d_nfg[b]) return;
    int a = d_fa[b*NA + j];
    int H, cell; float fs;
    anchor_info(a, H, fs, cell);
    const float* o = lvl_ptr(a, o0, o1, o2);
    int chs = H*H;
    int base = (b*NCH + 5)*chs + cell;
    float sqs = sqrtf(d_fsobj[b*NA + j]);
    float s = 0.f;
    #pragma unroll 4
    for (int c = 0; c < NC; ++c) {
        float xl = o[base + c*chs];
        float e = __expf(-xl);
        float p = sqs * rsqrtf(1.f + e);
        p = fminf(fmaxf(p, 1e-7f), 1.f - 1e-6f);
        float lm = __logf(1.f - p);
        float lp = __logf(p);
        s += lm;
        d_V[(b*NC + c)*NA + j] = lm - lp;
    }
    d_s[b*NA + j] = s;
}

// -------- K4: cost + iou matrix --------
__global__ void k_cost(const float* __restrict__ labels) {
    int b = blockIdx.y, g = blockIdx.x;
    if (!((d_vmask[b] >> g) & 1ull)) return;
    const float* L = labels + (b*NG + g)*5;
    int cls = (int)L[0];
    float gx = L[1], gy = L[2], gw = L[3], gh = L[4];
    float ga = gw*gh;
    float gx0 = gx - 0.5f*gw, gx1 = gx + 0.5f*gw;
    float gy0 = gy - 0.5f*gh, gy1 = gy + 0.5f*gh;
    int n = d_nfg[b];
    int rowbase = (b*NG + g)*NA;
    const float4* fbox = d_fbox + b*NA;
    const float* Vrow = d_V + (b*NC + cls)*NA;
    const float* srow = d_s + b*NA;
    const unsigned long long* grow = d_fgeom + b*NA;
    for (int j = threadIdx.x; j < n; j += blockDim.x) {
        float4 bx = fbox[j];
        float px0 = bx.x - 0.5f*bx.z, px1 = bx.x + 0.5f*bx.z;
        float py0 = bx.y - 0.5f*bx.w, py1 = bx.y + 0.5f*bx.w;
        float tlx = fmaxf(gx0, px0), tly = fmaxf(gy0, py0);
        float brx = fminf(gx1, px1), bry = fminf(gy1, py1);
        float en = (tlx < brx && tly < bry) ? 1.f : 0.f;
        float inter = (brx - tlx)*(bry - tly)*en;
        float iou = inter / (ga + bx.z*bx.w - inter + 1e-12f);
        float geomterm = ((grow[j] >> g) & 1ull) ? 0.f : 100000.f;
        float cost = Vrow[j] - srow[j] - 3.f*__logf(iou + 1e-8f) + geomterm;
        float2 ci; ci.x = cost; ci.y = iou;
        d_ci[rowbase + j] = ci;
    }
}

// -------- K5: per (b,g): dyn_k + threshold via warp shuffle-merge --------
__global__ void k_thr() {
    int b = blockIdx.y, g = blockIdx.x;
    int gi = b*NG + g;
    int lane = threadIdx.x;
    if (!((d_vmask[b] >> g) & 1ull)) {
        if (lane == 0) d_thr[gi] = -FLT_BIG;
        return;
    }
    int n = d_nfg[b];
    float ti[10], tc[10];
    #pragma unroll
    for (int i = 0; i < 10; ++i) { ti[i] = 0.f; tc[i] = FLT_BIG; }
    const float2* row = d_ci + (size_t)gi*NA;
    for (int j = lane; j < n; j += 32) {
        float2 ci = row[j];
        ins_max(ti, ci.y);
        ins_min(tc, ci.x);
    }
    #pragma unroll
    for (int off = 16; off >= 1; off >>= 1) {
        float ri[10], rc[10];
        #pragma unroll
        for (int i = 0; i < 10; ++i) {
            ri[i] = __shfl_down_sync(0xffffffffu, ti[i], off);
            rc[i] = __shfl_down_sync(0xffffffffu, tc[i], off);
        }
        #pragma unroll
        for (int i = 0; i < 10; ++i) { ins_max(ti, ri[i]); ins_min(tc, rc[i]); }
    }
    if (lane == 0) {
        float sum = 0.f;
        #pragma unroll
        for (int i = 0; i < 10; ++i) sum += ti[i];
        int dk = (int)sum;
        if (dk < 1) dk = 1;
        if (dk > 10) dk = 10;
        d_thr[gi] = tc[dk - 1];
    }
}

// -------- K6: final match + fg losses --------
__global__ void k_assign(const float* __restrict__ o0, const float* __restrict__ o1,
                         const float* __restrict__ o2, const float* __restrict__ labels) {
    int b = blockIdx.y;
    int j = blockIdx.x*blockDim.x + threadIdx.x;
    __shared__ float sthr[NG];
    if (threadIdx.x < NG) sthr[threadIdx.x] = d_thr[b*NG + threadIdx.x];
    __syncthreads();
    double li = 0.0, lo = 0.0, lc = 0.0, lf = 0.0;
    if (j < d_nfg[b]) {
        unsigned long long vm = d_vmask[b];
        unsigned long long mmask = 0ull;
        int cnt = 0, bestg = 0;
        float best = FLT_BIG;
        for (int g = 0; g < NG; ++g) {
            if (!((vm >> g) & 1ull)) continue;
            float c = d_ci[(b*NG + g)*NA + j].x;
            if (c < best) { best = c; bestg = g; }
            if (c <= sthr[g]) { mmask |= 1ull << g; cnt++; }
        }
        if (cnt > 1) mmask &= (1ull << bestg);
        if (mmask) {
            int mgt = __ffsll((long long)mmask) - 1;
            int a = d_fa[b*NA + j];
            float piou = d_ci[(b*NG + mgt)*NA + j].y;
            lf = 1.0;
            lo = -(double)d_objl[b*NA + a];
            const float* L = labels + (b*NG + mgt)*5;
            float tx = L[1], ty = L[2], tw = L[3], th = L[4];
            float4 pb = d_fbox[b*NA + j];
            float tlx = fmaxf(pb.x - 0.5f*pb.z, tx - 0.5f*tw);
            float tly = fmaxf(pb.y - 0.5f*pb.w, ty - 0.5f*th);
            float brx = fminf(pb.x + 0.5f*pb.z, tx + 0.5f*tw);
            float bry = fminf(pb.y + 0.5f*pb.w, ty + 0.5f*th);
            float en = (tlx < brx && tly < bry) ? 1.f : 0.f;
            float iw = fmaxf(brx - tlx, 0.f), ih = fmaxf(bry - tly, 0.f);
            float inter = iw*ih*en;
            float uni = pb.z*pb.w + tw*th - inter + 1e-16f;
            float iou = inter/uni;
            li = (double)(1.f - iou*iou);
            int mcls = (int)L[0];
            int H, cell; float fs;
            anchor_info(a, H, fs, cell);
            const float* o = lvl_ptr(a, o0, o1, o2);
            int chs = H*H;
            int base = (b*NCH + 5)*chs + cell;
            float csum = 0.f;
            #pragma unroll 4
            for (int c = 0; c < NC; ++c) {
                float xl = o[base + c*chs];
                csum += fmaxf(xl, 0.f) + __logf(1.f + __expf(-fabsf(xl)));
            }
            csum -= o[base + mcls*chs] * piou;
            lc = (double)csum;
        }
    }
    li = warp_sum(li); lo = warp_sum(lo); lc = warp_sum(lc); lf = warp_sum(lf);
    if ((threadIdx.x & 31) == 0) {
        if (li != 0.0) atomicAdd(&d_acc[0], li);
        if (lo != 0.0) atomicAdd(&d_acc[1], lo);
        if (lc != 0.0) atomicAdd(&d_acc[2], lc);
        if (lf != 0.0) atomicAdd(&d_acc[3], lf);
    }
}

// -------- K7: combine --------
__global__ void k_final(float* out) {
    double nf = d_acc[3];
    if (nf < 1.0) nf = 1.0;
    out[0] = (float)((5.0*d_acc[0] + d_acc[1] + d_acc[2]) / nf);
}

extern "C" void kernel_launch(void* const* d_in, const int* in_sizes, int n_in,
                              void* d_out, int out_size) {
    const float* o0 = (const float*)d_in[0];
    const float* o1 = (const float*)d_in[1];
    const float* o2 = (const float*)d_in[2];
    const float* lb = (const float*)d_in[3];

    k_init<<<NB, 64>>>(lb);
    k_anchor<<<dim3(NBLK, NB), 256>>>(o0, o1, o2, lb);
    k_compact<<<dim3(NBLK, NB), 256>>>();
    k_s<<<dim3((NA + 127)/128, NB), 128>>>(o0, o1, o2);
    k_cost<<<dim3(NG, NB), 128>>>(lb);
    k_thr<<<dim3(NG, NB), 32>>>();
    k_assign<<<dim3((NA + 127)/128, NB), 128>>>(o0, o1, o2, lb);
    k_final<<<1, 1>>>((float*)d_out);
}